// round 3
// baseline (speedup 1.0000x reference)
#include <cuda_runtime.h>
#include <cuda_bf16.h>

#define N_NODES 20000
#define N_EDGES 5000
#define STEPS 50
#define EDGE_STRIDE 128     // max nodes per edge (mean ~40)
#define NODE_STRIDE 64      // max edges per node (mean ~10)

#define NBLK 148            // <= SM count on GB300 -> all CTAs co-resident
#define NTHR 256
#define NWARPS (NBLK * (NTHR / 32))
#define NTHREADS_TOT (NBLK * NTHR)

// ---------------- scratch (device globals: no allocation allowed) ----------
__device__ int   g_edge_cnt[N_EDGES];
__device__ int   g_node_cnt[N_NODES];
__device__ int   g_edge_nodes[N_EDGES * EDGE_STRIDE];   // nodes in each edge
__device__ int   g_node_edges[N_NODES * NODE_STRIDE];   // edges touching each node
__device__ float g_agg[N_EDGES];                        // H @ I
__device__ float g_I[N_NODES];                          // current infected fraction

// grid barrier state (zero-initialized; returns to arrive=0 after each run,
// gen is monotonic so replays are safe)
__device__ unsigned g_bar_arrive;
__device__ unsigned g_bar_gen;

// ---------------- software grid barrier ------------------------------------
// All NBLK CTAs are guaranteed resident (grid <= #SMs, occupancy 1).
// Release ordering: __threadfence() (gpu scope) before arrive makes this
// block's prior stores globally visible; waiters spin on the volatile gen.
__device__ __forceinline__ void gsync() {
    __syncthreads();
    if (threadIdx.x == 0) {
        __threadfence();
        unsigned gen = *(volatile unsigned*)&g_bar_gen;
        if (atomicAdd(&g_bar_arrive, 1u) == NBLK - 1) {
            g_bar_arrive = 0;
            __threadfence();
            *(volatile unsigned*)&g_bar_gen = gen + 1;
        } else {
            while (*(volatile unsigned*)&g_bar_gen == gen) { }
        }
        __threadfence();   // acquire side: flush L1 so post-barrier reads are fresh
    }
    __syncthreads();
}

// ---------------- the whole problem in one launch ---------------------------
__global__ void __launch_bounds__(NTHR, 1)
sir_persistent(const float*  __restrict__ x,
               const float4* __restrict__ H4,
               const float*  __restrict__ beta,
               const float*  __restrict__ gamma,
               float*        __restrict__ out) {
    const int tid  = threadIdx.x;
    const int bid  = blockIdx.x;
    const int gt   = bid * NTHR + tid;
    const int lane = tid & 31;
    const int gw   = (gt >> 5);           // global warp id, 0..NWARPS-1

    // ---- phase 0: zero counters; load owned node state into registers ----
    for (int i = gt; i < N_EDGES; i += NTHREADS_TOT) g_edge_cnt[i] = 0;
    for (int i = gt; i < N_NODES; i += NTHREADS_TOT) g_node_cnt[i] = 0;

    const int n = gt;                     // owned node (one per thread)
    float S = 0.f, I = 0.f, R = 0.f, bn = 0.f, gn = 0.f;
    if (n < N_NODES) {
        S  = x[n * 3 + 0];
        I  = x[n * 3 + 1];
        R  = x[n * 3 + 2];
        bn = beta[n];
        gn = gamma[n];
        out[n * 3 + 0] = S;               // traj[0] = x
        out[n * 3 + 1] = I;
        out[n * 3 + 2] = R;
        g_I[n] = I;
    }
    gsync();

    // ---- phase 1: build sparse structure from dense H (400 MB scan) ------
    // H row-major [N_EDGES][N_NODES]; N_NODES % 4 == 0.
    {
        const int row4   = N_NODES / 4;           // 5000 float4 per edge row
        const int total4 = N_EDGES * row4;        // 25M
        for (int i = gt; i < total4; i += NTHREADS_TOT) {
            float4 v = H4[i];
            if (v.x != 0.f || v.y != 0.f || v.z != 0.f || v.w != 0.f) {
                int e  = i / row4;
                int nb = (i - e * row4) * 4;
                float vals[4] = {v.x, v.y, v.z, v.w};
                #pragma unroll
                for (int k = 0; k < 4; k++) {
                    if (vals[k] != 0.f) {
                        int nn = nb + k;
                        int p = atomicAdd(&g_edge_cnt[e], 1);
                        if (p < EDGE_STRIDE) g_edge_nodes[e * EDGE_STRIDE + p] = nn;
                        int q = atomicAdd(&g_node_cnt[nn], 1);
                        if (q < NODE_STRIDE) g_node_edges[nn * NODE_STRIDE + q] = e;
                    }
                }
            }
        }
    }
    gsync();

    // cache this thread's node-side adjacency metadata (immutable from here)
    int ncnt = 0;
    if (n < N_NODES) {
        ncnt = g_node_cnt[n];
        ncnt = (ncnt < NODE_STRIDE) ? ncnt : NODE_STRIDE;
    }

    // ---- phases 2..: 49 time steps, fully in-kernel ------------------------
    for (int t = 1; t < STEPS; t++) {
        // phase A: agg[e] = sum_{node in e} I[node]   (warp per edge)
        for (int e = gw; e < N_EDGES; e += NWARPS) {
            int cnt = __ldcg(&g_edge_cnt[e]);
            cnt = (cnt < EDGE_STRIDE) ? cnt : EDGE_STRIDE;
            float s = 0.f;
            for (int j = lane; j < cnt; j += 32)
                s += __ldcg(&g_I[g_edge_nodes[e * EDGE_STRIDE + j]]);
            #pragma unroll
            for (int o = 16; o; o >>= 1) s += __shfl_xor_sync(0xffffffffu, s, o);
            if (lane == 0) g_agg[e] = s;
        }
        gsync();

        // phase B: per-node backward gather + SIR update (state in registers)
        if (n < N_NODES) {
            float back = 0.f;
            #pragma unroll 4
            for (int j = 0; j < ncnt; j++)
                back += __ldcg(&g_agg[g_node_edges[n * NODE_STRIDE + j]]);

            float nc = bn * S * back;      // new cases
            float nr = gn * I;             // new recoveries

            float s0 = fmaxf(S - nc,      0.f);
            float s1 = fmaxf(I + nc - nr, 0.f);
            float s2 = fmaxf(R + nr,      0.f);
            float inv = 1.f / (s0 + s1 + s2);
            S = s0 * inv; I = s1 * inv; R = s2 * inv;

            float* cur = out + (long)t * (N_NODES * 3) + n * 3;
            cur[0] = S; cur[1] = I; cur[2] = R;
            g_I[n] = I;
        }
        gsync();
    }
}

// ---------------- launcher --------------------------------------------------
extern "C" void kernel_launch(void* const* d_in, const int* in_sizes, int n_in,
                              void* d_out, int out_size) {
    const float*  x     = (const float*) d_in[0];
    const float4* H4    = (const float4*)d_in[1];
    const float*  beta  = (const float*) d_in[2];
    const float*  gamma = (const float*) d_in[3];
    float*        out   = (float*)d_out;

    sir_persistent<<<NBLK, NTHR>>>(x, H4, beta, gamma, out);
}

// round 5
// speedup vs baseline: 1.6420x; 1.6420x over previous
#include <cuda_runtime.h>
#include <cuda_bf16.h>

#define N_NODES 20000
#define N_EDGES 5000
#define STEPS 50
#define EDGE_STRIDE 128     // max nodes per edge (mean ~40)
#define NODE_STRIDE 64      // max edges per node (mean ~10)

// persistent step kernel shape: all CTAs co-resident (grid <= #SMs, occ 1)
#define NBLK 148
#define NTHR 512
#define NWARPS (NBLK * (NTHR / 32))
#define NTHREADS_TOT (NBLK * NTHR)

// ---------------- scratch (device globals: no allocation allowed) ----------
__device__ int   g_edge_cnt[N_EDGES];
__device__ int   g_node_cnt[N_NODES];
__device__ int   g_edge_nodes[N_EDGES * EDGE_STRIDE];   // nodes in each edge
__device__ int   g_node_edges[N_NODES * NODE_STRIDE];   // edges touching each node
__device__ float g_agg[N_EDGES];                        // H @ I
__device__ float g_I[N_NODES];                          // current infected fraction

// grid barrier state (arrive returns to 0 each barrier; gen is monotonic so
// graph replays are safe)
__device__ unsigned g_bar_arrive;
__device__ unsigned g_bar_gen;

// ---------------- init: zero counters, traj[0] = x, seed g_I ----------------
__global__ void k_init(const float* __restrict__ x, float* __restrict__ out) {
    int i = blockIdx.x * blockDim.x + threadIdx.x;
    if (i < N_EDGES) g_edge_cnt[i] = 0;
    if (i < N_NODES) {
        g_node_cnt[i] = 0;
        float s  = x[i * 3 + 0];
        float in = x[i * 3 + 1];
        float r  = x[i * 3 + 2];
        out[i * 3 + 0] = s;
        out[i * 3 + 1] = in;
        out[i * 3 + 2] = r;
        g_I[i] = in;
    }
}

// ---------------- build sparse structure (big grid -> full HBM bandwidth) --
// H row-major [N_EDGES][N_NODES]; N_NODES % 4 == 0 so float4 stays in-row.
__global__ void k_build(const float4* __restrict__ H4) {
    const int row4   = N_NODES / 4;            // 5000 float4 per edge row
    const int total4 = N_EDGES * row4;         // 25M
    int stride = gridDim.x * blockDim.x;
    for (int i = blockIdx.x * blockDim.x + threadIdx.x; i < total4; i += stride) {
        float4 v = H4[i];
        if (v.x != 0.f || v.y != 0.f || v.z != 0.f || v.w != 0.f) {
            int e  = i / row4;
            int nb = (i - e * row4) * 4;
            float vals[4] = {v.x, v.y, v.z, v.w};
            #pragma unroll
            for (int k = 0; k < 4; k++) {
                if (vals[k] != 0.f) {
                    int nn = nb + k;
                    int p = atomicAdd(&g_edge_cnt[e], 1);
                    if (p < EDGE_STRIDE) g_edge_nodes[e * EDGE_STRIDE + p] = nn;
                    int q = atomicAdd(&g_node_cnt[nn], 1);
                    if (q < NODE_STRIDE) g_node_edges[nn * NODE_STRIDE + q] = e;
                }
            }
        }
    }
}

// ---------------- software grid barrier (148 co-resident CTAs) --------------
__device__ __forceinline__ void gsync() {
    __syncthreads();
    if (threadIdx.x == 0) {
        __threadfence();
        unsigned gen = *(volatile unsigned*)&g_bar_gen;
        if (atomicAdd(&g_bar_arrive, 1u) == NBLK - 1) {
            g_bar_arrive = 0;
            __threadfence();
            *(volatile unsigned*)&g_bar_gen = gen + 1;
        } else {
            while (*(volatile unsigned*)&g_bar_gen == gen) { }
        }
        __threadfence();
    }
    __syncthreads();
}

// ---------------- all 49 steps in one persistent launch ---------------------
__global__ void __launch_bounds__(NTHR, 1)
sir_steps(const float* __restrict__ x,
          const float* __restrict__ beta,
          const float* __restrict__ gamma,
          float*       __restrict__ out) {
    const int tid  = threadIdx.x;
    const int gt   = blockIdx.x * NTHR + tid;
    const int lane = tid & 31;
    const int gw   = gt >> 5;             // global warp id

    // owned node state in registers for all 49 steps
    const int n = gt;
    float S = 0.f, I = 0.f, R = 0.f, bn = 0.f, gn = 0.f;
    int   ncnt = 0;
    if (n < N_NODES) {
        S  = x[n * 3 + 0];
        I  = x[n * 3 + 1];
        R  = x[n * 3 + 2];
        bn = beta[n];
        gn = gamma[n];
        ncnt = g_node_cnt[n];             // written by k_build (prior launch)
        ncnt = (ncnt < NODE_STRIDE) ? ncnt : NODE_STRIDE;
    }

    for (int t = 1; t < STEPS; t++) {
        // phase A: agg[e] = sum_{node in e} I[node]  (warp per edge)
        for (int e = gw; e < N_EDGES; e += NWARPS) {
            int cnt = g_edge_cnt[e];      // immutable: plain (L1) load
            cnt = (cnt < EDGE_STRIDE) ? cnt : EDGE_STRIDE;
            float s = 0.f;
            for (int j = lane; j < cnt; j += 32)
                s += __ldcg(&g_I[g_edge_nodes[e * EDGE_STRIDE + j]]);
            #pragma unroll
            for (int o = 16; o; o >>= 1) s += __shfl_xor_sync(0xffffffffu, s, o);
            if (lane == 0) g_agg[e] = s;
        }
        gsync();

        // phase B: backward gather + SIR update (state in registers)
        if (n < N_NODES) {
            float back = 0.f;
            #pragma unroll 4
            for (int j = 0; j < ncnt; j++)
                back += __ldcg(&g_agg[g_node_edges[n * NODE_STRIDE + j]]);

            float nc = bn * S * back;     // new cases
            float nr = gn * I;            // new recoveries

            float s0 = fmaxf(S - nc,      0.f);
            float s1 = fmaxf(I + nc - nr, 0.f);
            float s2 = fmaxf(R + nr,      0.f);
            float inv = 1.f / (s0 + s1 + s2);
            S = s0 * inv; I = s1 * inv; R = s2 * inv;

            float* cur = out + (long)t * (N_NODES * 3) + n * 3;
            cur[0] = S; cur[1] = I; cur[2] = R;
            g_I[n] = I;
        }
        gsync();
    }
}

// ---------------- launcher --------------------------------------------------
extern "C" void kernel_launch(void* const* d_in, const int* in_sizes, int n_in,
                              void* d_out, int out_size) {
    const float*  x     = (const float*) d_in[0];
    const float4* H4    = (const float4*)d_in[1];
    const float*  beta  = (const float*) d_in[2];
    const float*  gamma = (const float*) d_in[3];
    float*        out   = (float*)d_out;

    k_init <<<(N_NODES + 255) / 256, 256>>>(x, out);
    k_build<<<4096, 256>>>(H4);
    sir_steps<<<NBLK, NTHR>>>(x, beta, gamma, out);
}